// round 7
// baseline (speedup 1.0000x reference)
#include <cuda_runtime.h>
#include <cuda_fp16.h>
#include <cstdint>

// ---------------- problem constants ----------------
#define T_TOKENS 16384
#define DMODEL   2048
#define NEXP     64
#define MT       64
#define NCTAS    (T_TOKENS / MT)      // 256
#define NTHREADS 256
#define BK       32
#define KT       (DMODEL / BK)        // 64
#define SCALE    2048.0f
#define INVS     (1.0f / 2048.0f)

// ---------------- output layout (fp32, reference return order) ----------------
#define OFF_W    ((size_t)0)
#define OFF_I    ((size_t)32768)
#define OFF_P    ((size_t)65536)
#define OFF_ENT  ((size_t)1114112)
#define OFF_CONF ((size_t)1114113)
#define OFF_UTIL ((size_t)1114114)

// ---------------- smem layout ----------------
// rows padded to 80B: row stride mod 128 cycles through 8 distinct 16B groups
// -> conflict-free ldmatrix without XOR swizzle.
#define ASTR     80
#define AH_OFF   0
#define AM_OFF   (64 * ASTR)                // 5120
#define BH_OFF   (2 * 64 * ASTR)            // 10240
#define BM_OFF   (3 * 64 * ASTR)            // 15360
#define BUF_BYTES (4 * 64 * ASTR)           // 20480
#define DSM_BYTES (2 * BUF_BYTES)           // 40960
#define LSTR     66                          // logits row stride (floats)

// ---------------- device globals ----------------
__device__ float  g_ent;
__device__ float  g_conf;
__device__ int    g_counts[NEXP];
__device__ int    g_done;

// ---------------- helpers ----------------
__device__ __forceinline__ uint32_t smem_u32(const void* p) {
    uint32_t a;
    asm("{ .reg .u64 t; cvta.to.shared.u64 t, %1; cvt.u32.u64 %0, t; }" : "=r"(a) : "l"(p));
    return a;
}
#define STS128(addr, a, b, c, d) \
    asm volatile("st.shared.v4.b32 [%0], {%1,%2,%3,%4};" :: "r"(addr), "r"(a), "r"(b), "r"(c), "r"(d) : "memory")

__device__ __forceinline__ void ldsm4(uint32_t& r0, uint32_t& r1, uint32_t& r2, uint32_t& r3, uint32_t a) {
    asm volatile("ldmatrix.sync.aligned.m8n8.x4.shared.b16 {%0,%1,%2,%3}, [%4];"
                 : "=r"(r0), "=r"(r1), "=r"(r2), "=r"(r3) : "r"(a));
}
__device__ __forceinline__ void mma16816(float* c, const uint32_t* a, const uint32_t* b) {
    asm volatile("mma.sync.aligned.m16n8k16.row.col.f32.f16.f16.f32 "
                 "{%0,%1,%2,%3},{%4,%5,%6,%7},{%8,%9},{%0,%1,%2,%3};"
                 : "+f"(c[0]), "+f"(c[1]), "+f"(c[2]), "+f"(c[3])
                 : "r"(a[0]), "r"(a[1]), "r"(a[2]), "r"(a[3]), "r"(b[0]), "r"(b[1]));
}

// two-limb fp16 split of a float pair -> packed H and scaled-M half2s
__device__ __forceinline__ void cvt2(float a, float b, uint32_t& H, uint32_t& M) {
    __half2 h = __floats2half2_rn(a, b);
    float2 hf = __half22float2(h);
    __half2 m = __floats2half2_rn((a - hf.x) * SCALE, (b - hf.y) * SCALE);
    H = *reinterpret_cast<uint32_t*>(&h);
    M = *reinterpret_cast<uint32_t*>(&m);
}

// strict ordering with lowest-index tie-break (matches jax top_k)
__device__ __forceinline__ bool ordgt(float a, int ia, float b, int ib) {
    return (a > b) || (a == b && ia < ib);
}

// ---------------- zero stats ----------------
__global__ void zero_kernel() {
    int t = threadIdx.x;
    if (t == 0) { g_ent = 0.0f; g_conf = 0.0f; g_done = 0; }
    if (t < NEXP) g_counts[t] = 0;
}

// ---------------- main fused router ----------------
__global__ __launch_bounds__(NTHREADS, 2)
void router_kernel(const float* __restrict__ x, const float* __restrict__ W,
                   float* __restrict__ out) {
    extern __shared__ __align__(16) char dsm[];
    __shared__ int hist[NEXP];
    __shared__ int s_last;

    const int t    = threadIdx.x;
    const int wid  = t >> 5;
    const int lane = t & 31;
    const int mbase = blockIdx.x * MT;
    const uint32_t smbase = smem_u32(dsm);

    if (t < NEXP) hist[t] = 0;

    // load-thread assignments (256 threads): 8 floats per thread per operand
    const int xr = t >> 2;            // token / expert row 0..63
    const int xq = t & 3;             // 8-float chunk of 32-k slice

    // warp tile: 2 m-warps x 4 n-warps, each M32 x N16
    const int wm = (wid >> 2) * 32;
    const int wn = (wid & 3) * 16;

    // per-lane ldmatrix byte offsets
    const uint32_t a_l_off = (uint32_t)((lane & 15) * ASTR + (lane >> 4) * 16);
    const uint32_t b_l_off = (uint32_t)(((lane & 7) + ((lane >> 4) & 1) * 8) * ASTR + ((lane >> 3) & 1) * 16);

    float c0[2][2][4], c1[2][2][4];
    #pragma unroll
    for (int i = 0; i < 2; i++)
        #pragma unroll
        for (int j = 0; j < 2; j++)
            #pragma unroll
            for (int k = 0; k < 4; k++) { c0[i][j][k] = 0.0f; c1[i][j][k] = 0.0f; }

    const float* xp = x + (size_t)(mbase + xr) * DMODEL + xq * 8;
    const float* wp = W + (size_t)xr * DMODEL + xq * 8;

    // prefetch tile 0
    float4 xv0 = ((const float4*)xp)[0];
    float4 xv1 = ((const float4*)xp)[1];
    float4 wv0 = ((const float4*)wp)[0];
    float4 wv1 = ((const float4*)wp)[1];

    const uint32_t aH = smbase + AH_OFF + (uint32_t)(xr * ASTR + xq * 16);
    const uint32_t aM = smbase + AM_OFF + (uint32_t)(xr * ASTR + xq * 16);
    const uint32_t bH = smbase + BH_OFF + (uint32_t)(xr * ASTR + xq * 16);
    const uint32_t bM = smbase + BM_OFF + (uint32_t)(xr * ASTR + xq * 16);

    for (int tile = 0; tile < KT; tile++) {
        const uint32_t bufoff = (tile & 1) * BUF_BYTES;

        // ---- convert staged x and W -> limbs, store swizzle-free padded rows ----
        {
            uint32_t H[4], M[4];
            cvt2(xv0.x, xv0.y, H[0], M[0]); cvt2(xv0.z, xv0.w, H[1], M[1]);
            cvt2(xv1.x, xv1.y, H[2], M[2]); cvt2(xv1.z, xv1.w, H[3], M[3]);
            STS128(aH + bufoff, H[0], H[1], H[2], H[3]);
            STS128(aM + bufoff, M[0], M[1], M[2], M[3]);
            cvt2(wv0.x, wv0.y, H[0], M[0]); cvt2(wv0.z, wv0.w, H[1], M[1]);
            cvt2(wv1.x, wv1.y, H[2], M[2]); cvt2(wv1.z, wv1.w, H[3], M[3]);
            STS128(bH + bufoff, H[0], H[1], H[2], H[3]);
            STS128(bM + bufoff, M[0], M[1], M[2], M[3]);
        }

        // ---- prefetch next tile ----
        if (tile + 1 < KT) {
            const float* xn = xp + (tile + 1) * BK;
            xv0 = ((const float4*)xn)[0];
            xv1 = ((const float4*)xn)[1];
            const float* wn_ = wp + (tile + 1) * BK;
            wv0 = ((const float4*)wn_)[0];
            wv1 = ((const float4*)wn_)[1];
        }

        __syncthreads();   // single barrier per tile (double buffer covers WAR)

        const uint32_t bb = smbase + bufoff;

        // ---- compute: 2 k16 steps, 3 limb products, M32xN16 per warp ----
        #pragma unroll
        for (int ks = 0; ks < 2; ks++) {
            uint32_t ah[2][4], am[2][4], bh[2][2], bm[2][2];
            #pragma unroll
            for (int mt = 0; mt < 2; mt++) {
                uint32_t ab = bb + (uint32_t)((wm + mt * 16) * ASTR) + a_l_off + ks * 32;
                ldsm4(ah[mt][0], ah[mt][1], ah[mt][2], ah[mt][3], ab + AH_OFF);
                ldsm4(am[mt][0], am[mt][1], am[mt][2], am[mt][3], ab + AM_OFF);
            }
            {
                uint32_t nb = bb + (uint32_t)(wn * ASTR) + b_l_off + ks * 32;
                uint32_t r0, r1, r2, r3;
                ldsm4(r0, r1, r2, r3, nb + BH_OFF);
                bh[0][0] = r0; bh[0][1] = r1; bh[1][0] = r2; bh[1][1] = r3;
                ldsm4(r0, r1, r2, r3, nb + BM_OFF);
                bm[0][0] = r0; bm[0][1] = r1; bm[1][0] = r2; bm[1][1] = r3;
            }
            #pragma unroll
            for (int mt = 0; mt < 2; mt++)
                #pragma unroll
                for (int nt = 0; nt < 2; nt++) {
                    mma16816(c0[mt][nt], ah[mt], bh[nt]);
                    mma16816(c1[mt][nt], ah[mt], bm[nt]);
                    mma16816(c1[mt][nt], am[mt], bh[nt]);
                }
        }
    }

    // ---- dump combined logits to smem (overlay buffer 0 region) ----
    __syncthreads();
    float* Lsm = reinterpret_cast<float*>(dsm);
    #pragma unroll
    for (int mt = 0; mt < 2; mt++)
        #pragma unroll
        for (int nt = 0; nt < 2; nt++) {
            int r0 = wm + mt * 16 + (lane >> 2);
            int cc = wn + nt * 8 + (lane & 3) * 2;
            Lsm[r0 * LSTR + cc]           = c0[mt][nt][0] + c1[mt][nt][0] * INVS;
            Lsm[r0 * LSTR + cc + 1]       = c0[mt][nt][1] + c1[mt][nt][1] * INVS;
            Lsm[(r0 + 8) * LSTR + cc]     = c0[mt][nt][2] + c1[mt][nt][2] * INVS;
            Lsm[(r0 + 8) * LSTR + cc + 1] = c0[mt][nt][3] + c1[mt][nt][3] * INVS;
        }
    __syncthreads();

    // ---- epilogue: 4 threads per token, 16 experts each ----
    const int q  = t & 3;            // expert quarter
    const int tl = t >> 2;           // token local 0..63
    const int tok = mbase + tl;
    const float* L = &Lsm[tl * LSTR + q * 16];

    // local top-2 over this quarter
    float m1 = -1e30f, m2 = -1e30f;
    int i1 = q * 16, i2 = q * 16;
    #pragma unroll
    for (int e = 0; e < 16; e++) {
        float v = L[e];
        int id = q * 16 + e;
        if (v > m1)      { m2 = m1; i2 = i1; m1 = v; i1 = id; }
        else if (v > m2) { m2 = v;  i2 = id; }
    }

    // butterfly merge across the 4 quarter-lanes (same warp)
    #pragma unroll
    for (int o = 1; o <= 2; o <<= 1) {
        float om1 = __shfl_xor_sync(0xffffffffu, m1, o);
        float om2 = __shfl_xor_sync(0xffffffffu, m2, o);
        int   oi1 = __shfl_xor_sync(0xffffffffu, i1, o);
        int   oi2 = __shfl_xor_sync(0xffffffffu, i2, o);
        if (ordgt(om1, oi1, m1, i1)) {
            if (ordgt(m1, i1, om2, oi2)) { m2 = m1; i2 = i1; }
            else                         { m2 = om2; i2 = oi2; }
            m1 = om1; i1 = oi1;
        } else {
            if (ordgt(om1, oi1, m2, i2)) { m2 = om1; i2 = oi1; }
        }
    }

    // softmax partial Z over local 16 (global max m1)
    float ex[16];
    float Z = 0.0f;
    #pragma unroll
    for (int e = 0; e < 16; e++) {
        ex[e] = __expf(L[e] - m1);
        Z += ex[e];
    }
    Z += __shfl_xor_sync(0xffffffffu, Z, 1);
    Z += __shfl_xor_sync(0xffffffffu, Z, 2);
    const float invZ = 1.0f / Z;

    // probs + partial entropy
    float ent = 0.0f;
    float4* dst = reinterpret_cast<float4*>(out + OFF_P + (size_t)tok * NEXP + q * 16);
    #pragma unroll
    for (int i = 0; i < 4; i++) {
        float p0 = ex[4*i+0] * invZ;
        float p1 = ex[4*i+1] * invZ;
        float p2 = ex[4*i+2] * invZ;
        float p3 = ex[4*i+3] * invZ;
        ent -= p0 * __logf(p0 + 1e-10f) + p1 * __logf(p1 + 1e-10f)
             + p2 * __logf(p2 + 1e-10f) + p3 * __logf(p3 + 1e-10f);
        dst[i] = make_float4(p0, p1, p2, p3);
    }
    ent += __shfl_xor_sync(0xffffffffu, ent, 1);
    ent += __shfl_xor_sync(0xffffffffu, ent, 2);

    // weights / indices / per-token stats (quarter 0 only)
    float conf = 0.0f;
    if (q == 0) {
        float ed = __expf(m2 - m1);
        float w0 = 1.0f / (1.0f + ed);
        float w1 = ed * w0;
        *reinterpret_cast<float2*>(out + OFF_W + (size_t)tok * 2) = make_float2(w0, w1);
        *reinterpret_cast<float2*>(out + OFF_I + (size_t)tok * 2) = make_float2((float)i1, (float)i2);
        conf = w0;
        atomicAdd(&hist[i1], 1);
        atomicAdd(&hist[i2], 1);
    } else {
        ent = 0.0f;
    }

    // warp-reduce ent/conf -> global atomics
    #pragma unroll
    for (int o = 16; o > 0; o >>= 1) {
        ent  += __shfl_down_sync(0xffffffffu, ent,  o);
        conf += __shfl_down_sync(0xffffffffu, conf, o);
    }
    if (lane == 0) { atomicAdd(&g_ent, ent); atomicAdd(&g_conf, conf); }

    __syncthreads();
    if (t < NEXP) { int c = hist[t]; if (c) atomicAdd(&g_counts[t], c); }

    // ---- last-CTA finalize ----
    __syncthreads();
    if (t == 0) {
        __threadfence();
        s_last = (atomicAdd(&g_done, 1) == NCTAS - 1) ? 1 : 0;
    }
    __syncthreads();
    if (s_last) {
        __threadfence();
        if (t == 0) {
            out[OFF_ENT]  = atomicAdd(&g_ent,  0.0f) * (1.0f / 16384.0f);
            out[OFF_CONF] = atomicAdd(&g_conf, 0.0f) * (1.0f / 16384.0f);
        }
        if (t < NEXP)
            out[OFF_UTIL + t] = (float)atomicAdd(&g_counts[t], 0) * (1.0f / 32768.0f);
    }
}

extern "C" void kernel_launch(void* const* d_in, const int* in_sizes, int n_in,
                              void* d_out, int out_size) {
    const float* x = (const float*)d_in[0];   // [4,4096,2048] fp32
    const float* W = (const float*)d_in[1];   // [64,2048] fp32
    float* out = (float*)d_out;

    cudaFuncSetAttribute(router_kernel, cudaFuncAttributeMaxDynamicSharedMemorySize, DSM_BYTES);

    zero_kernel<<<1, 64>>>();
    router_kernel<<<NCTAS, NTHREADS, DSM_BYTES>>>(x, W, out);
}

// round 8
// speedup vs baseline: 1.1447x; 1.1447x over previous
#include <cuda_runtime.h>
#include <cuda_fp16.h>
#include <cstdint>

// ---------------- problem constants ----------------
#define T_TOKENS 16384
#define DMODEL   2048
#define NEXP     64
#define MT       64
#define NCTAS    (T_TOKENS / MT)      // 256
#define NTHREADS 256
#define BK       32
#define KT       (DMODEL / BK)        // 64
#define SCALE    2048.0f
#define INVS     (1.0f / 2048.0f)

// ---------------- output layout (fp32, reference return order) ----------------
#define OFF_W    ((size_t)0)
#define OFF_I    ((size_t)32768)
#define OFF_P    ((size_t)65536)
#define OFF_ENT  ((size_t)1114112)
#define OFF_CONF ((size_t)1114113)
#define OFF_UTIL ((size_t)1114114)

// ---------------- smem layout ----------------
// rows padded to 80B: stride mod 128 cycles 8 distinct 16B groups -> conflict-free ldmatrix.
#define ASTR     80
#define AH_OFF   0
#define AM_OFF   (64 * ASTR)                // 5120
#define BH_OFF   (2 * 64 * ASTR)            // 10240
#define BM_OFF   (3 * 64 * ASTR)            // 15360
#define BUF_BYTES (4 * 64 * ASTR)           // 20480
#define DSM_BYTES (2 * BUF_BYTES)           // 40960
#define LSTR     66                          // logits row stride (floats)

// ---------------- device globals ----------------
__device__ __half g_Wh[NEXP * DMODEL];
__device__ __half g_Wm[NEXP * DMODEL];
__device__ float  g_ent;
__device__ float  g_conf;
__device__ int    g_counts[NEXP];
__device__ int    g_done;

// ---------------- helpers ----------------
__device__ __forceinline__ uint32_t smem_u32(const void* p) {
    uint32_t a;
    asm("{ .reg .u64 t; cvta.to.shared.u64 t, %1; cvt.u32.u64 %0, t; }" : "=r"(a) : "l"(p));
    return a;
}
#define STS128(addr, a, b, c, d) \
    asm volatile("st.shared.v4.b32 [%0], {%1,%2,%3,%4};" :: "r"(addr), "r"(a), "r"(b), "r"(c), "r"(d) : "memory")
#define CP_ASYNC16(dst, src) \
    asm volatile("cp.async.cg.shared.global [%0], [%1], 16;" :: "r"(dst), "l"(src) : "memory")
#define CP_COMMIT() asm volatile("cp.async.commit_group;" ::: "memory")
#define CP_WAIT0()  asm volatile("cp.async.wait_group 0;" ::: "memory")

__device__ __forceinline__ void ldsm4(uint32_t& r0, uint32_t& r1, uint32_t& r2, uint32_t& r3, uint32_t a) {
    asm volatile("ldmatrix.sync.aligned.m8n8.x4.shared.b16 {%0,%1,%2,%3}, [%4];"
                 : "=r"(r0), "=r"(r1), "=r"(r2), "=r"(r3) : "r"(a));
}
__device__ __forceinline__ void mma16816(float* c, const uint32_t* a, const uint32_t* b) {
    asm volatile("mma.sync.aligned.m16n8k16.row.col.f32.f16.f16.f32 "
                 "{%0,%1,%2,%3},{%4,%5,%6,%7},{%8,%9},{%0,%1,%2,%3};"
                 : "+f"(c[0]), "+f"(c[1]), "+f"(c[2]), "+f"(c[3])
                 : "r"(a[0]), "r"(a[1]), "r"(a[2]), "r"(a[3]), "r"(b[0]), "r"(b[1]));
}

// two-limb fp16 split of a float pair -> packed H and scaled-M half2s
__device__ __forceinline__ void cvt2(float a, float b, uint32_t& H, uint32_t& M) {
    __half2 h = __floats2half2_rn(a, b);
    float2 hf = __half22float2(h);
    __half2 m = __floats2half2_rn((a - hf.x) * SCALE, (b - hf.y) * SCALE);
    H = *reinterpret_cast<uint32_t*>(&h);
    M = *reinterpret_cast<uint32_t*>(&m);
}

// strict ordering with lowest-index tie-break (matches jax top_k)
__device__ __forceinline__ bool ordgt(float a, int ia, float b, int ib) {
    return (a > b) || (a == b && ia < ib);
}

// ---------------- prep: zero stats + split W into fp16 limbs ----------------
__global__ void prep_kernel(const float* __restrict__ W) {
    if (blockIdx.x == 0) {
        if (threadIdx.x == 0) { g_ent = 0.0f; g_conf = 0.0f; g_done = 0; }
        if (threadIdx.x < NEXP) g_counts[threadIdx.x] = 0;
    }
    int i = (blockIdx.x * 256 + threadIdx.x) * 4;
    if (i < NEXP * DMODEL) {
        float4 f = *(const float4*)(W + i);
        uint32_t h0, m0, h1, m1;
        cvt2(f.x, f.y, h0, m0);
        cvt2(f.z, f.w, h1, m1);
        *(uint2*)(g_Wh + i) = make_uint2(h0, h1);
        *(uint2*)(g_Wm + i) = make_uint2(m0, m1);
    }
}

// ---------------- main fused router ----------------
__global__ __launch_bounds__(NTHREADS, 2)
void router_kernel(const float* __restrict__ x, float* __restrict__ out) {
    extern __shared__ __align__(16) char dsm[];
    __shared__ int hist[NEXP];
    __shared__ int s_last;

    const int t    = threadIdx.x;
    const int wid  = t >> 5;
    const int lane = t & 31;
    const int mbase = blockIdx.x * MT;
    const uint32_t smbase = smem_u32(dsm);

    if (t < NEXP) hist[t] = 0;

    // A staging: thread -> (row, 8-float chunk)
    const int xr = t >> 2;            // token row 0..63
    const int xq = t & 3;             // 8-float chunk of 32-k slice

    // B cp.async: thread -> (row 0..63, 16B chunk 0..3) for both limbs
    const int br = t >> 2;
    const int bc = t & 3;
    const uint32_t bDstH = smbase + BH_OFF + (uint32_t)(br * ASTR + bc * 16);
    const uint32_t bDstM = smbase + BM_OFF + (uint32_t)(br * ASTR + bc * 16);
    const __half* bSrcH = g_Wh + (size_t)br * DMODEL + bc * 8;
    const __half* bSrcM = g_Wm + (size_t)br * DMODEL + bc * 8;

    // K-specialized warps: warps 0-3 -> ks=0, warps 4-7 -> ks=1; grid 2m x 2n, M32xN32
    const int ks = wid >> 2;
    const int wq = wid & 3;
    const int wm = (wq >> 1) * 32;
    const int wn = (wq & 1) * 32;

    // per-lane ldmatrix byte offsets
    const uint32_t a_l_off = (uint32_t)((lane & 15) * ASTR + (lane >> 4) * 16) + (uint32_t)(ks * 32);
    const uint32_t b_l_off = (uint32_t)(((lane & 7) + ((lane >> 4) & 1) * 8) * ASTR + ((lane >> 3) & 1) * 16) + (uint32_t)(ks * 32);

    float c0[2][4][4], c1[2][4][4];
    #pragma unroll
    for (int i = 0; i < 2; i++)
        #pragma unroll
        for (int j = 0; j < 4; j++)
            #pragma unroll
            for (int k = 0; k < 4; k++) { c0[i][j][k] = 0.0f; c1[i][j][k] = 0.0f; }

    const float* xp = x + (size_t)(mbase + xr) * DMODEL + xq * 8;
    const uint32_t aH = smbase + AH_OFF + (uint32_t)(xr * ASTR + xq * 16);
    const uint32_t aM = smbase + AM_OFF + (uint32_t)(xr * ASTR + xq * 16);

    // prologue: B(0) via cp.async, A(0) staged in regs
    CP_ASYNC16(bDstH, bSrcH);
    CP_ASYNC16(bDstM, bSrcM);
    CP_COMMIT();
    float4 xv0 = ((const float4*)xp)[0];
    float4 xv1 = ((const float4*)xp)[1];

    for (int tile = 0; tile < KT; tile++) {
        const uint32_t bufoff = (tile & 1) * BUF_BYTES;

        // ---- convert staged x -> limbs, store ----
        {
            uint32_t H[4], M[4];
            cvt2(xv0.x, xv0.y, H[0], M[0]); cvt2(xv0.z, xv0.w, H[1], M[1]);
            cvt2(xv1.x, xv1.y, H[2], M[2]); cvt2(xv1.z, xv1.w, H[3], M[3]);
            STS128(aH + bufoff, H[0], H[1], H[2], H[3]);
            STS128(aM + bufoff, M[0], M[1], M[2], M[3]);
        }

        // ---- stage next A ----
        if (tile + 1 < KT) {
            const float* xn = xp + (tile + 1) * BK;
            xv0 = ((const float4*)xn)[0];
            xv1 = ((const float4*)xn)[1];
        }

        CP_WAIT0();        // B(tile) landed
        __syncthreads();   // everyone's A stores + B visible; prev compute done

        // ---- issue B(tile+1) async into the other buffer (post-barrier: no WAR) ----
        if (tile + 1 < KT) {
            const uint32_t nb = (uint32_t)(((tile + 1) & 1) * BUF_BYTES);
            const size_t so = (size_t)(tile + 1) * BK;
            CP_ASYNC16(bDstH + nb, bSrcH + so);
            CP_ASYNC16(bDstM + nb, bSrcM + so);
            CP_COMMIT();
        }

        const uint32_t bb = smbase + bufoff;

        // ---- compute this warp's k16 step: M32xN32, 3 limb products ----
        uint32_t ah[2][4], am[2][4], bh[4][2], bm[4][2];
        #pragma unroll
        for (int mt = 0; mt < 2; mt++) {
            uint32_t ab = bb + (uint32_t)((wm + mt * 16) * ASTR) + a_l_off;
            ldsm4(ah[mt][0], ah[mt][1], ah[mt][2], ah[mt][3], ab + AH_OFF);
            ldsm4(am[mt][0], am[mt][1], am[mt][2], am[mt][3], ab + AM_OFF);
        }
        #pragma unroll
        for (int np = 0; np < 2; np++) {
            uint32_t nb2 = bb + (uint32_t)((wn + np * 16) * ASTR) + b_l_off;
            uint32_t r0, r1, r2, r3;
            ldsm4(r0, r1, r2, r3, nb2 + BH_OFF);
            bh[np*2][0] = r0; bh[np*2][1] = r1; bh[np*2+1][0] = r2; bh[np*2+1][1] = r3;
            ldsm4(r0, r1, r2, r3, nb2 + BM_OFF);
            bm[np*2][0] = r0; bm[np*2][1] = r1; bm[np*2+1][0] = r2; bm[np*2+1][1] = r3;
        }
        #pragma unroll
        for (int mt = 0; mt < 2; mt++)
            #pragma unroll
            for (int nt = 0; nt < 4; nt++) {
                mma16816(c0[mt][nt], ah[mt], bh[nt]);
                mma16816(c1[mt][nt], ah[mt], bm[nt]);
                mma16816(c1[mt][nt], am[mt], bh[nt]);
            }
    }

    // ---- merge k-halves into logits smem: ks0 warps write, ks1 warps add ----
    __syncthreads();
    float* Lsm = reinterpret_cast<float*>(dsm);
    if (ks == 0) {
        #pragma unroll
        for (int mt = 0; mt < 2; mt++)
            #pragma unroll
            for (int nt = 0; nt < 4; nt++) {
                int r0 = wm + mt * 16 + (lane >> 2);
                int cc = wn + nt * 8 + (lane & 3) * 2;
                Lsm[r0 * LSTR + cc]           = c0[mt][nt][0] + c1[mt][nt][0] * INVS;
                Lsm[r0 * LSTR + cc + 1]       = c0[mt][nt][1] + c1[mt][nt][1] * INVS;
                Lsm[(r0 + 8) * LSTR + cc]     = c0[mt][nt][2] + c1[mt][nt][2] * INVS;
                Lsm[(r0 + 8) * LSTR + cc + 1] = c0[mt][nt][3] + c1[mt][nt][3] * INVS;
            }
    }
    __syncthreads();
    if (ks == 1) {
        #pragma unroll
        for (int mt = 0; mt < 2; mt++)
            #pragma unroll
            for (int nt = 0; nt < 4; nt++) {
                int r0 = wm + mt * 16 + (lane >> 2);
                int cc = wn + nt * 8 + (lane & 3) * 2;
                Lsm[r0 * LSTR + cc]           += c0[mt][nt][0] + c1[mt][nt][0] * INVS;
                Lsm[r0 * LSTR + cc + 1]       += c0[mt][nt][1] + c1[mt][nt][1] * INVS;
                Lsm[(r0 + 8) * LSTR + cc]     += c0[mt][nt][2] + c1[mt][nt][2] * INVS;
                Lsm[(r0 + 8) * LSTR + cc + 1] += c0[mt][nt][3] + c1[mt][nt][3] * INVS;
            }
    }
    __syncthreads();

    // ---- epilogue: 4 threads per token, 16 experts each ----
    const int q  = t & 3;
    const int tl = t >> 2;           // token local 0..63
    const int tok = mbase + tl;
    const float* L = &Lsm[tl * LSTR + q * 16];

    float m1 = -1e30f, m2 = -1e30f;
    int i1 = q * 16, i2 = q * 16;
    #pragma unroll
    for (int e = 0; e < 16; e++) {
        float v = L[e];
        int id = q * 16 + e;
        if (v > m1)      { m2 = m1; i2 = i1; m1 = v; i1 = id; }
        else if (v > m2) { m2 = v;  i2 = id; }
    }

    #pragma unroll
    for (int o = 1; o <= 2; o <<= 1) {
        float om1 = __shfl_xor_sync(0xffffffffu, m1, o);
        float om2 = __shfl_xor_sync(0xffffffffu, m2, o);
        int   oi1 = __shfl_xor_sync(0xffffffffu, i1, o);
        int   oi2 = __shfl_xor_sync(0xffffffffu, i2, o);
        if (ordgt(om1, oi1, m1, i1)) {
            if (ordgt(m1, i1, om2, oi2)) { m2 = m1; i2 = i1; }
            else                         { m2 = om2; i2 = oi2; }
            m1 = om1; i1 = oi1;
        } else {
            if (ordgt(om1, oi1, m2, i2)) { m2 = om1; i2 = oi1; }
        }
    }

    float ex[16];
    float Z = 0.0f;
    #pragma unroll
    for (int e = 0; e < 16; e++) {
        ex[e] = __expf(L[e] - m1);
        Z += ex[e];
    }
    Z += __shfl_xor_sync(0xffffffffu, Z, 1);
    Z += __shfl_xor_sync(0xffffffffu, Z, 2);
    const float invZ = 1.0f / Z;

    float ent = 0.0f;
    float4* dst = reinterpret_cast<float4*>(out + OFF_P + (size_t)tok * NEXP + q * 16);
    #pragma unroll
    for (int i = 0; i < 4; i++) {
        float p0 = ex[4*i+0] * invZ;
        float p1 = ex[4*i+1] * invZ;
        float p2 = ex[4*i+2] * invZ;
        float p3 = ex[4*i+3] * invZ;
        ent -= p0 * __logf(p0 + 1e-10f) + p1 * __logf(p1 + 1e-10f)
             + p2 * __logf(p2 + 1e-10f) + p3 * __logf(p3 + 1e-10f);
        dst[i] = make_float4(p0, p1, p2, p3);
    }
    ent += __shfl_xor_sync(0xffffffffu, ent, 1);
    ent += __shfl_xor_sync(0xffffffffu, ent, 2);

    float conf = 0.0f;
    if (q == 0) {
        float ed = __expf(m2 - m1);
        float w0 = 1.0f / (1.0f + ed);
        float w1 = ed * w0;
        *reinterpret_cast<float2*>(out + OFF_W + (size_t)tok * 2) = make_float2(w0, w1);
        *reinterpret_cast<float2*>(out + OFF_I + (size_t)tok * 2) = make_float2((float)i1, (float)i2);
        conf = w0;
        atomicAdd(&hist[i1], 1);
        atomicAdd(&hist[i2], 1);
    } else {
        ent = 0.0f;
    }

    #pragma unroll
    for (int o = 16; o > 0; o >>= 1) {
        ent  += __shfl_down_sync(0xffffffffu, ent,  o);
        conf += __shfl_down_sync(0xffffffffu, conf, o);
    }
    if (lane == 0) { atomicAdd(&g_ent, ent); atomicAdd(&g_conf, conf); }

    __syncthreads();
    if (t < NEXP) { int c = hist[t]; if (c) atomicAdd(&g_counts[t], c); }

    // ---- last-CTA finalize ----
    __syncthreads();
    if (t == 0) {
        __threadfence();
        s_last = (atomicAdd(&g_done, 1) == NCTAS - 1) ? 1 : 0;
    }
    __syncthreads();
    if (s_last) {
        __threadfence();
        if (t == 0) {
            out[OFF_ENT]  = atomicAdd(&g_ent,  0.0f) * (1.0f / 16384.0f);
            out[OFF_CONF] = atomicAdd(&g_conf, 0.0f) * (1.0f / 16384.0f);
        }
        if (t < NEXP)
            out[OFF_UTIL + t] = (float)atomicAdd(&g_counts[t], 0) * (1.0f / 32768.0f);
    }
}

extern "C" void kernel_launch(void* const* d_in, const int* in_sizes, int n_in,
                              void* d_out, int out_size) {
    const float* x = (const float*)d_in[0];   // [4,4096,2048] fp32
    const float* W = (const float*)d_in[1];   // [64,2048] fp32
    float* out = (float*)d_out;

    cudaFuncSetAttribute(router_kernel, cudaFuncAttributeMaxDynamicSharedMemorySize, DSM_BYTES);

    prep_kernel<<<128, 256>>>(W);
    router_kernel<<<NCTAS, NTHREADS, DSM_BYTES>>>(x, out);
}

// round 9
// speedup vs baseline: 1.2180x; 1.0640x over previous
#include <cuda_runtime.h>
#include <cuda_fp16.h>
#include <cstdint>

// ---------------- problem constants ----------------
#define T_TOKENS 16384
#define DMODEL   2048
#define NEXP     64
#define MT       64
#define NCTAS    (T_TOKENS / MT)      // 256
#define NTHREADS 256
#define BK       32
#define KT       (DMODEL / BK)        // 64
#define SCALE    2048.0f
#define INVS     (1.0f / 2048.0f)

// ---------------- output layout (fp32, reference return order) ----------------
#define OFF_W    ((size_t)0)
#define OFF_I    ((size_t)32768)
#define OFF_P    ((size_t)65536)
#define OFF_ENT  ((size_t)1114112)
#define OFF_CONF ((size_t)1114113)
#define OFF_UTIL ((size_t)1114114)

// ---------------- smem layout ----------------
// rows padded to 80B: stride mod 128 cycles 8 distinct 16B groups -> conflict-free ldmatrix.
#define ASTR     80
#define AH_OFF   0
#define AM_OFF   (64 * ASTR)                // 5120
#define BH_OFF   (2 * 64 * ASTR)            // 10240
#define BM_OFF   (3 * 64 * ASTR)            // 15360
#define BUF_BYTES (4 * 64 * ASTR)           // 20480
#define DSM_BYTES (2 * BUF_BYTES)           // 40960
#define LSTR     66                          // logits row stride (floats)

// ---------------- device globals ----------------
__device__ __half g_Wh[NEXP * DMODEL];
__device__ __half g_Wm[NEXP * DMODEL];
__device__ float  g_ent;
__device__ float  g_conf;
__device__ int    g_counts[NEXP];
__device__ int    g_done;

// ---------------- helpers ----------------
__device__ __forceinline__ uint32_t smem_u32(const void* p) {
    uint32_t a;
    asm("{ .reg .u64 t; cvta.to.shared.u64 t, %1; cvt.u32.u64 %0, t; }" : "=r"(a) : "l"(p));
    return a;
}
#define STS128(addr, a, b, c, d) \
    asm volatile("st.shared.v4.b32 [%0], {%1,%2,%3,%4};" :: "r"(addr), "r"(a), "r"(b), "r"(c), "r"(d) : "memory")
#define CP_ASYNC16(dst, src) \
    asm volatile("cp.async.cg.shared.global [%0], [%1], 16;" :: "r"(dst), "l"(src) : "memory")
#define CP_COMMIT() asm volatile("cp.async.commit_group;" ::: "memory")
#define CP_WAIT0()  asm volatile("cp.async.wait_group 0;" ::: "memory")

__device__ __forceinline__ void ldsm4(uint32_t& r0, uint32_t& r1, uint32_t& r2, uint32_t& r3, uint32_t a) {
    asm volatile("ldmatrix.sync.aligned.m8n8.x4.shared.b16 {%0,%1,%2,%3}, [%4];"
                 : "=r"(r0), "=r"(r1), "=r"(r2), "=r"(r3) : "r"(a));
}
__device__ __forceinline__ void mma16816(float* c, const uint32_t* a, const uint32_t* b) {
    asm volatile("mma.sync.aligned.m16n8k16.row.col.f32.f16.f16.f32 "
                 "{%0,%1,%2,%3},{%4,%5,%6,%7},{%8,%9},{%0,%1,%2,%3};"
                 : "+f"(c[0]), "+f"(c[1]), "+f"(c[2]), "+f"(c[3])
                 : "r"(a[0]), "r"(a[1]), "r"(a[2]), "r"(a[3]), "r"(b[0]), "r"(b[1]));
}

// two-limb fp16 split of a float pair -> packed H and scaled-M half2s
__device__ __forceinline__ void cvt2(float a, float b, uint32_t& H, uint32_t& M) {
    __half2 h = __floats2half2_rn(a, b);
    float2 hf = __half22float2(h);
    __half2 m = __floats2half2_rn((a - hf.x) * SCALE, (b - hf.y) * SCALE);
    H = *reinterpret_cast<uint32_t*>(&h);
    M = *reinterpret_cast<uint32_t*>(&m);
}

// strict ordering with lowest-index tie-break (matches jax top_k)
__device__ __forceinline__ bool ordgt(float a, int ia, float b, int ib) {
    return (a > b) || (a == b && ia < ib);
}

// ---------------- prep: zero stats + split W into fp16 limbs ----------------
__global__ void prep_kernel(const float* __restrict__ W) {
    if (blockIdx.x == 0) {
        if (threadIdx.x == 0) { g_ent = 0.0f; g_conf = 0.0f; g_done = 0; }
        if (threadIdx.x < NEXP) g_counts[threadIdx.x] = 0;
    }
    int i = (blockIdx.x * 256 + threadIdx.x) * 4;
    if (i < NEXP * DMODEL) {
        float4 f = *(const float4*)(W + i);
        uint32_t h0, m0, h1, m1;
        cvt2(f.x, f.y, h0, m0);
        cvt2(f.z, f.w, h1, m1);
        *(uint2*)(g_Wh + i) = make_uint2(h0, h1);
        *(uint2*)(g_Wm + i) = make_uint2(m0, m1);
    }
}

// ---------------- main fused router ----------------
__global__ __launch_bounds__(NTHREADS, 2)
void router_kernel(const float* __restrict__ x, float* __restrict__ out) {
    extern __shared__ __align__(16) char dsm[];
    __shared__ int hist[NEXP];
    __shared__ int s_last;

    const int t    = threadIdx.x;
    const int wid  = t >> 5;
    const int lane = t & 31;
    const int mbase = blockIdx.x * MT;
    const uint32_t smbase = smem_u32(dsm);

    if (t < NEXP) hist[t] = 0;

    // A staging: thread -> (row, 8-float chunk)
    const int xr = t >> 2;            // token row 0..63
    const int xq = t & 3;             // 8-float chunk of 32-k slice

    // B cp.async: thread -> (row 0..63, 16B chunk 0..3) for both limbs
    const int br = t >> 2;
    const int bc = t & 3;
    const uint32_t bDstH = smbase + BH_OFF + (uint32_t)(br * ASTR + bc * 16);
    const uint32_t bDstM = smbase + BM_OFF + (uint32_t)(br * ASTR + bc * 16);
    const __half* bSrcH = g_Wh + (size_t)br * DMODEL + bc * 8;
    const __half* bSrcM = g_Wm + (size_t)br * DMODEL + bc * 8;

    // K-specialized warps: warps 0-3 -> ks=0, warps 4-7 -> ks=1; grid 2m x 2n, M32xN32
    const int ks = wid >> 2;
    const int wq = wid & 3;
    const int wm = (wq >> 1) * 32;
    const int wn = (wq & 1) * 32;

    // per-lane ldmatrix byte offsets
    const uint32_t a_l_off = (uint32_t)((lane & 15) * ASTR + (lane >> 4) * 16) + (uint32_t)(ks * 32);
    const uint32_t b_l_off = (uint32_t)(((lane & 7) + ((lane >> 4) & 1) * 8) * ASTR + ((lane >> 3) & 1) * 16) + (uint32_t)(ks * 32);

    float c0[2][4][4], c1[2][4][4];
    #pragma unroll
    for (int i = 0; i < 2; i++)
        #pragma unroll
        for (int j = 0; j < 4; j++)
            #pragma unroll
            for (int k = 0; k < 4; k++) { c0[i][j][k] = 0.0f; c1[i][j][k] = 0.0f; }

    const float* xp = x + (size_t)(mbase + xr) * DMODEL + xq * 8;
    const uint32_t aH = smbase + AH_OFF + (uint32_t)(xr * ASTR + xq * 16);
    const uint32_t aM = smbase + AM_OFF + (uint32_t)(xr * ASTR + xq * 16);

    // ---- prologue: fill buf0 with tile 0 (A + B); stage x(1) in regs ----
    float4 xv0 = ((const float4*)xp)[0];
    float4 xv1 = ((const float4*)xp)[1];
    {
        uint32_t H[4], M[4];
        cvt2(xv0.x, xv0.y, H[0], M[0]); cvt2(xv0.z, xv0.w, H[1], M[1]);
        cvt2(xv1.x, xv1.y, H[2], M[2]); cvt2(xv1.z, xv1.w, H[3], M[3]);
        STS128(aH, H[0], H[1], H[2], H[3]);
        STS128(aM, M[0], M[1], M[2], M[3]);
    }
    CP_ASYNC16(bDstH, bSrcH);
    CP_ASYNC16(bDstM, bSrcM);
    CP_COMMIT();
    xv0 = ((const float4*)(xp + BK))[0];
    xv1 = ((const float4*)(xp + BK))[1];
    CP_WAIT0();
    __syncthreads();   // tile 0 published

    // ---- mainloop: store tile i+1, compute tile i ----
    for (int tile = 0; tile < KT; tile++) {
        const uint32_t cur = smbase + (tile & 1) * BUF_BYTES;
        const uint32_t nxtoff = ((tile + 1) & 1) * BUF_BYTES;

        if (tile + 1 < KT) {
            // B(i+1) async into opposite buffer (safe: compute(i-1) done per last sync)
            const size_t so = (size_t)(tile + 1) * BK;
            CP_ASYNC16(bDstH + nxtoff, bSrcH + so);
            CP_ASYNC16(bDstM + nxtoff, bSrcM + so);
            CP_COMMIT();
            // A(i+1): convert staged regs -> limbs, store into opposite buffer
            uint32_t H[4], M[4];
            cvt2(xv0.x, xv0.y, H[0], M[0]); cvt2(xv0.z, xv0.w, H[1], M[1]);
            cvt2(xv1.x, xv1.y, H[2], M[2]); cvt2(xv1.z, xv1.w, H[3], M[3]);
            STS128(aH + nxtoff, H[0], H[1], H[2], H[3]);
            STS128(aM + nxtoff, M[0], M[1], M[2], M[3]);
        }
        if (tile + 2 < KT) {
            const float* xn = xp + (tile + 2) * BK;
            xv0 = ((const float4*)xn)[0];
            xv1 = ((const float4*)xn)[1];
        }

        // ---- compute tile i from cur (data resident since previous iteration) ----
        uint32_t ah[2][4], am[2][4], bh[4][2], bm[4][2];
        #pragma unroll
        for (int mt = 0; mt < 2; mt++) {
            uint32_t ab = cur + (uint32_t)((wm + mt * 16) * ASTR) + a_l_off;
            ldsm4(ah[mt][0], ah[mt][1], ah[mt][2], ah[mt][3], ab + AH_OFF);
            ldsm4(am[mt][0], am[mt][1], am[mt][2], am[mt][3], ab + AM_OFF);
        }
        #pragma unroll
        for (int np = 0; np < 2; np++) {
            uint32_t nb2 = cur + (uint32_t)((wn + np * 16) * ASTR) + b_l_off;
            uint32_t r0, r1, r2, r3;
            ldsm4(r0, r1, r2, r3, nb2 + BH_OFF);
            bh[np*2][0] = r0; bh[np*2][1] = r1; bh[np*2+1][0] = r2; bh[np*2+1][1] = r3;
            ldsm4(r0, r1, r2, r3, nb2 + BM_OFF);
            bm[np*2][0] = r0; bm[np*2][1] = r1; bm[np*2+1][0] = r2; bm[np*2+1][1] = r3;
        }
        #pragma unroll
        for (int mt = 0; mt < 2; mt++)
            #pragma unroll
            for (int nt = 0; nt < 4; nt++) {
                mma16816(c0[mt][nt], ah[mt], bh[nt]);
                mma16816(c1[mt][nt], ah[mt], bm[nt]);
                mma16816(c1[mt][nt], am[mt], bh[nt]);
            }

        if (tile + 1 < KT) CP_WAIT0();   // B(i+1) landed
        __syncthreads();                  // publish A/B(i+1); close compute(i)
    }

    // ---- merge k-halves into logits smem: ks0 warps write, ks1 warps add ----
    float* Lsm = reinterpret_cast<float*>(dsm);
    if (ks == 0) {
        #pragma unroll
        for (int mt = 0; mt < 2; mt++)
            #pragma unroll
            for (int nt = 0; nt < 4; nt++) {
                int r0 = wm + mt * 16 + (lane >> 2);
                int cc = wn + nt * 8 + (lane & 3) * 2;
                Lsm[r0 * LSTR + cc]           = c0[mt][nt][0] + c1[mt][nt][0] * INVS;
                Lsm[r0 * LSTR + cc + 1]       = c0[mt][nt][1] + c1[mt][nt][1] * INVS;
                Lsm[(r0 + 8) * LSTR + cc]     = c0[mt][nt][2] + c1[mt][nt][2] * INVS;
                Lsm[(r0 + 8) * LSTR + cc + 1] = c0[mt][nt][3] + c1[mt][nt][3] * INVS;
            }
    }
    __syncthreads();
    if (ks == 1) {
        #pragma unroll
        for (int mt = 0; mt < 2; mt++)
            #pragma unroll
            for (int nt = 0; nt < 4; nt++) {
                int r0 = wm + mt * 16 + (lane >> 2);
                int cc = wn + nt * 8 + (lane & 3) * 2;
                Lsm[r0 * LSTR + cc]           += c0[mt][nt][0] + c1[mt][nt][0] * INVS;
                Lsm[r0 * LSTR + cc + 1]       += c0[mt][nt][1] + c1[mt][nt][1] * INVS;
                Lsm[(r0 + 8) * LSTR + cc]     += c0[mt][nt][2] + c1[mt][nt][2] * INVS;
                Lsm[(r0 + 8) * LSTR + cc + 1] += c0[mt][nt][3] + c1[mt][nt][3] * INVS;
            }
    }
    __syncthreads();

    // ---- epilogue: 4 threads per token, 16 experts each ----
    const int q  = t & 3;
    const int tl = t >> 2;           // token local 0..63
    const int tok = mbase + tl;
    const float* L = &Lsm[tl * LSTR + q * 16];

    float m1 = -1e30f, m2 = -1e30f;
    int i1 = q * 16, i2 = q * 16;
    #pragma unroll
    for (int e = 0; e < 16; e++) {
        float v = L[e];
        int id = q * 16 + e;
        if (v > m1)      { m2 = m1; i2 = i1; m1 = v; i1 = id; }
        else if (v > m2) { m2 = v;  i2 = id; }
    }

    #pragma unroll
    for (int o = 1; o <= 2; o <<= 1) {
        float om1 = __shfl_xor_sync(0xffffffffu, m1, o);
        float om2 = __shfl_xor_sync(0xffffffffu, m2, o);
        int   oi1 = __shfl_xor_sync(0xffffffffu, i1, o);
        int   oi2 = __shfl_xor_sync(0xffffffffu, i2, o);
        if (ordgt(om1, oi1, m1, i1)) {
            if (ordgt(m1, i1, om2, oi2)) { m2 = m1; i2 = i1; }
            else                         { m2 = om2; i2 = oi2; }
            m1 = om1; i1 = oi1;
        } else {
            if (ordgt(om1, oi1, m2, i2)) { m2 = om1; i2 = oi1; }
        }
    }

    float ex[16];
    float Z = 0.0f;
    #pragma unroll
    for (int e = 0; e < 16; e++) {
        ex[e] = __expf(L[e] - m1);
        Z += ex[e];
    }
    Z += __shfl_xor_sync(0xffffffffu, Z, 1);
    Z += __shfl_xor_sync(0xffffffffu, Z, 2);
    const float invZ = 1.0f / Z;

    float ent = 0.0f;
    float4* dst = reinterpret_cast<float4*>(out + OFF_P + (size_t)tok * NEXP + q * 16);
    #pragma unroll
    for (int i = 0; i < 4; i++) {
        float p0 = ex[4*i+0] * invZ;
        float p1 = ex[4*i+1] * invZ;
        float p2 = ex[4*i+2] * invZ;
        float p3 = ex[4*i+3] * invZ;
        ent -= p0 * __logf(p0 + 1e-10f) + p1 * __logf(p1 + 1e-10f)
             + p2 * __logf(p2 + 1e-10f) + p3 * __logf(p3 + 1e-10f);
        dst[i] = make_float4(p0, p1, p2, p3);
    }
    ent += __shfl_xor_sync(0xffffffffu, ent, 1);
    ent += __shfl_xor_sync(0xffffffffu, ent, 2);

    float conf = 0.0f;
    if (q == 0) {
        float ed = __expf(m2 - m1);
        float w0 = 1.0f / (1.0f + ed);
        float w1 = ed * w0;
        *reinterpret_cast<float2*>(out + OFF_W + (size_t)tok * 2) = make_float2(w0, w1);
        *reinterpret_cast<float2*>(out + OFF_I + (size_t)tok * 2) = make_float2((float)i1, (float)i2);
        conf = w0;
        atomicAdd(&hist[i1], 1);
        atomicAdd(&hist[i2], 1);
    } else {
        ent = 0.0f;
    }

    #pragma unroll
    for (int o = 16; o > 0; o >>= 1) {
        ent  += __shfl_down_sync(0xffffffffu, ent,  o);
        conf += __shfl_down_sync(0xffffffffu, conf, o);
    }
    if (lane == 0) { atomicAdd(&g_ent, ent); atomicAdd(&g_conf, conf); }

    __syncthreads();
    if (t < NEXP) { int c = hist[t]; if (c) atomicAdd(&g_counts[t], c); }

    // ---- last-CTA finalize ----
    __syncthreads();
    if (t == 0) {
        __threadfence();
        s_last = (atomicAdd(&g_done, 1) == NCTAS - 1) ? 1 : 0;
    }
    __syncthreads();
    if (s_last) {
        __threadfence();
        if (t == 0) {
            out[OFF_ENT]  = atomicAdd(&g_ent,  0.0f) * (1.0f / 16384.0f);
            out[OFF_CONF] = atomicAdd(&g_conf, 0.0f) * (1.0f / 16384.0f);
        }
        if (t < NEXP)
            out[OFF_UTIL + t] = (float)atomicAdd(&g_counts[t], 0) * (1.0f / 32768.0f);
    }
}

extern "C" void kernel_launch(void* const* d_in, const int* in_sizes, int n_in,
                              void* d_out, int out_size) {
    const float* x = (const float*)d_in[0];   // [4,4096,2048] fp32
    const float* W = (const float*)d_in[1];   // [64,2048] fp32
    float* out = (float*)d_out;

    cudaFuncSetAttribute(router_kernel, cudaFuncAttributeMaxDynamicSharedMemorySize, DSM_BYTES);

    prep_kernel<<<128, 256>>>(W);
    router_kernel<<<NCTAS, NTHREADS, DSM_BYTES>>>(x, out);
}